// round 15
// baseline (speedup 1.0000x reference)
#include <cuda_runtime.h>
#include <cuda_fp16.h>
#include <cstdint>

#define BB 4
#define SS 2048
#define DM 1024
#define HH 16
#define DK 64
#define MROWS (BB * SS)   // 8192
#define NX ((size_t)MROWS * DM)   // 8388608
#define NW ((size_t)DM * DM)      // 1048576

// scratch (allocation-free rule: __device__ globals)
__device__ __half   g_qh[BB * HH * SS * DK];   // pre-scaled by 0.125*log2(e)
__device__ __half   g_kh[BB * HH * SS * DK];
__device__ __half   g_vh[BB * HH * SS * DK];
__device__ __half   g_ct[BB * SS * DM];        // fp16 concat
__device__ __half   g_x3[3 * NX];              // fp16 q|k|v
__device__ __half   g_w4[4 * NW];              // fp16 Wq|Wk|Wv|Wo
__device__ uint32_t g_mb[BB * SS * (SS / 32)]; // bit-packed mask (2MB)

#define QSCALE (0.125f * 1.44269504088896f)    // 1/sqrt(dk) * log2(e)

// ---------------------------------------------------------------------------
// helpers
// ---------------------------------------------------------------------------
__device__ __forceinline__ void ldsm_x4(uint32_t* r, uint32_t addr) {
    asm volatile("ldmatrix.sync.aligned.m8n8.x4.shared.b16 {%0,%1,%2,%3}, [%4];"
                 : "=r"(r[0]), "=r"(r[1]), "=r"(r[2]), "=r"(r[3]) : "r"(addr));
}

__device__ __forceinline__ void ldsm_x4_t(uint32_t* r, uint32_t addr) {
    asm volatile("ldmatrix.sync.aligned.m8n8.x4.trans.shared.b16 {%0,%1,%2,%3}, [%4];"
                 : "=r"(r[0]), "=r"(r[1]), "=r"(r[2]), "=r"(r[3]) : "r"(addr));
}

__device__ __forceinline__ void mma_f16(float* c, const uint32_t* a,
                                        uint32_t b0, uint32_t b1) {
    asm volatile(
        "mma.sync.aligned.m16n8k16.row.col.f32.f16.f16.f32 "
        "{%0,%1,%2,%3},{%4,%5,%6,%7},{%8,%9},{%0,%1,%2,%3};"
        : "+f"(c[0]), "+f"(c[1]), "+f"(c[2]), "+f"(c[3])
        : "r"(a[0]), "r"(a[1]), "r"(a[2]), "r"(a[3]), "r"(b0), "r"(b1));
}

__device__ __forceinline__ uint32_t pack_h2(float lo, float hi) {
    __half2 h = __floats2half2_rn(lo, hi);
    return *(uint32_t*)&h;
}

__device__ __forceinline__ void cp16(uint32_t dst, const void* src) {
    asm volatile("cp.async.ca.shared.global [%0], [%1], 16;"
                 :: "r"(dst), "l"(src));
}

__device__ __forceinline__ float ex2f(float x) {
    float r;
    asm("ex2.approx.ftz.f32 %0, %1;" : "=f"(r) : "f"(x));
    return r;
}

// ---------------------------------------------------------------------------
// one-shot fp32 -> fp16 for q,k,v,Wq,Wk,Wv,Wo (8 elems/thread)
// ---------------------------------------------------------------------------
__global__ void convert_all(const float* __restrict__ q, const float* __restrict__ k,
                            const float* __restrict__ v, const float* __restrict__ Wq,
                            const float* __restrict__ Wk, const float* __restrict__ Wv,
                            const float* __restrict__ Wo) {
    const size_t i = ((size_t)blockIdx.x * blockDim.x + threadIdx.x) * 8;
    const float* src;
    __half* dst;
    if (i < NX)            { src = q  + i;           dst = g_x3 + i; }
    else if (i < 2 * NX)   { src = k  + (i - NX);    dst = g_x3 + i; }
    else if (i < 3 * NX)   { src = v  + (i - 2*NX);  dst = g_x3 + i; }
    else {
        const size_t j = i - 3 * NX;
        if (j < NW)          { src = Wq + j;          dst = g_w4 + j; }
        else if (j < 2 * NW) { src = Wk + (j - NW);   dst = g_w4 + j; }
        else if (j < 3 * NW) { src = Wv + (j - 2*NW); dst = g_w4 + j; }
        else                 { src = Wo + (j - 3*NW); dst = g_w4 + j; }
    }
    const float4 a = *(const float4*)(src);
    const float4 b = *(const float4*)(src + 4);
    __half2 h[4];
    h[0] = __floats2half2_rn(a.x, a.y);
    h[1] = __floats2half2_rn(a.z, a.w);
    h[2] = __floats2half2_rn(b.x, b.y);
    h[3] = __floats2half2_rn(b.z, b.w);
    *(uint4*)dst = *(const uint4*)h;
}

// ---------------------------------------------------------------------------
// mask bit-pack
// ---------------------------------------------------------------------------
__global__ void pack_mask(const int* __restrict__ mask, uint32_t* __restrict__ mb) {
    const size_t g = (size_t)blockIdx.x * blockDim.x + threadIdx.x;
    const uint32_t word = __ballot_sync(0xffffffffu, mask[g] != 0);
    if ((threadIdx.x & 31) == 0) mb[g >> 5] = word;
}

// ---------------------------------------------------------------------------
// fp16 GEMM core (R13-validated): 128x128x32 CTA tile, 128 threads
// (4 warps 2x2), 64x64 warp tile, m16n8k16, cp.async double buffer.
// ---------------------------------------------------------------------------
#define KPH 40

// Batched QKV projection: grid.z in {0,1,2} selects X slice, W slice, bias,
// destination (head-layout fp16), and scale. Core loop identical to R13.
__global__ void __launch_bounds__(128, 2) gemm_qkv(
    const float* __restrict__ bq,
    const float* __restrict__ bk,
    const float* __restrict__ bv)
{
    __shared__ __half Ah[2][128 * KPH];
    __shared__ __half Bh[2][128 * KPH];

    const int tid  = threadIdx.x;
    const int lane = tid & 31;
    const int warp = tid >> 5;
    const int wm   = warp >> 1;
    const int wn   = warp & 1;
    const int m0   = blockIdx.x * 128;
    const int e0   = blockIdx.y * 128;
    const int z    = blockIdx.z;

    const __half* X = g_x3 + (size_t)z * NX;
    const __half* W = g_w4 + (size_t)z * NW;
    const float* bias = (z == 0) ? bq : (z == 1) ? bk : bv;
    __half* Y = (z == 0) ? g_qh : (z == 1) ? g_kh : g_vh;
    const float scale = (z == 0) ? QSCALE : 1.0f;

    const uint32_t aBase = (uint32_t)__cvta_generic_to_shared(&Ah[0][0]);
    const uint32_t bBase = (uint32_t)__cvta_generic_to_shared(&Bh[0][0]);
    const uint32_t bufB  = 128 * KPH * 2;

    const __half* Xp = X + (size_t)m0 * DM;
    const __half* Wp = W + (size_t)e0 * DM;

    float c[4][8][4];
    #pragma unroll
    for (int i = 0; i < 4; i++)
        #pragma unroll
        for (int j = 0; j < 8; j++)
            #pragma unroll
            for (int r = 0; r < 4; r++) c[i][j][r] = 0.f;

    const int aRow = (lane & 15);
    const int aCol = ((lane >> 4) & 1) * 8;
    const int bRow = (lane & 7) + ((lane >> 4) << 3);
    const int bK   = ((lane >> 3) & 1) * 8;

    {
        #pragma unroll
        for (int t = 0; t < 4; t++) {
            const int ch = t * 128 + tid;
            const int r = ch >> 2, c8 = (ch & 3) << 3;
            cp16(aBase + 2u * (r * KPH + c8), Xp + (size_t)r * DM + c8);
            cp16(bBase + 2u * (r * KPH + c8), Wp + (size_t)r * DM + c8);
        }
        asm volatile("cp.async.commit_group;");
    }

    int buf = 0;
    for (int kt = 0; kt < DM / 32; kt++) {
        asm volatile("cp.async.wait_group 0;");
        __syncthreads();

        if (kt + 1 < DM / 32) {
            const int k0 = (kt + 1) * 32;
            const uint32_t ao = aBase + (buf ^ 1) * bufB;
            const uint32_t bo = bBase + (buf ^ 1) * bufB;
            #pragma unroll
            for (int t = 0; t < 4; t++) {
                const int ch = t * 128 + tid;
                const int r = ch >> 2, c8 = (ch & 3) << 3;
                cp16(ao + 2u * (r * KPH + c8), Xp + (size_t)r * DM + k0 + c8);
                cp16(bo + 2u * (r * KPH + c8), Wp + (size_t)r * DM + k0 + c8);
            }
            asm volatile("cp.async.commit_group;");
        }

        const uint32_t ab = aBase + buf * bufB;
        const uint32_t bb = bBase + buf * bufB;
        #pragma unroll
        for (int kc = 0; kc < 2; kc++) {
            uint32_t afr[4][4], bfr[4][4];
            #pragma unroll
            for (int mt = 0; mt < 4; mt++)
                ldsm_x4(afr[mt], ab + 2u * ((wm * 64 + mt * 16 + aRow) * KPH
                                            + aCol + kc * 16));
            #pragma unroll
            for (int nq = 0; nq < 4; nq++)
                ldsm_x4(bfr[nq], bb + 2u * ((wn * 64 + nq * 16 + bRow) * KPH
                                            + bK + kc * 16));
            #pragma unroll
            for (int mt = 0; mt < 4; mt++)
                #pragma unroll
                for (int nt = 0; nt < 8; nt++)
                    mma_f16(c[mt][nt], afr[mt],
                            bfr[nt >> 1][(nt & 1) * 2],
                            bfr[nt >> 1][(nt & 1) * 2 + 1]);
        }
        buf ^= 1;
    }

    // epilogue: fp16 head layout
    #pragma unroll
    for (int mt = 0; mt < 4; mt++) {
        #pragma unroll
        for (int nt = 0; nt < 8; nt++) {
            const int row = m0 + wm * 64 + mt * 16 + (lane >> 2);
            const int col = e0 + wn * 64 + nt * 8 + 2 * (lane & 3);
            const float2 bv2 = *(const float2*)(bias + col);
            const int h = col >> 6, d = col & 63;
            const int b0_ = row >> 11, s0 = row & (SS - 1);
            __half2 h0 = __floats2half2_rn((c[mt][nt][0] + bv2.x) * scale,
                                           (c[mt][nt][1] + bv2.y) * scale);
            __half2 h1 = __floats2half2_rn((c[mt][nt][2] + bv2.x) * scale,
                                           (c[mt][nt][3] + bv2.y) * scale);
            *(__half2*)(Y + ((size_t)((b0_ * HH + h) * SS + s0)) * DK + d) = h0;
            *(__half2*)(Y + ((size_t)((b0_ * HH + h) * SS + s0 + 8)) * DK + d) = h1;
        }
    }
}

// Output projection: fp32 row-major out (R13 gemm_f16<false> body).
__global__ void __launch_bounds__(128, 2) gemm_out(
    const __half* __restrict__ X,     // [MROWS, DM] fp16 (ct)
    const __half* __restrict__ W,     // [DM, DM] fp16 (Wo)
    const float* __restrict__ bias,
    float* __restrict__ Y)
{
    __shared__ __half Ah[2][128 * KPH];
    __shared__ __half Bh[2][128 * KPH];

    const int tid  = threadIdx.x;
    const int lane = tid & 31;
    const int warp = tid >> 5;
    const int wm   = warp >> 1;
    const int wn   = warp & 1;
    const int m0   = blockIdx.x * 128;
    const int e0   = blockIdx.y * 128;

    const uint32_t aBase = (uint32_t)__cvta_generic_to_shared(&Ah[0][0]);
    const uint32_t bBase = (uint32_t)__cvta_generic_to_shared(&Bh[0][0]);
    const uint32_t bufB  = 128 * KPH * 2;

    const __half* Xp = X + (size_t)m0 * DM;
    const __half* Wp = W + (size_t)e0 * DM;

    float c[4][8][4];
    #pragma unroll
    for (int i = 0; i < 4; i++)
        #pragma unroll
        for (int j = 0; j < 8; j++)
            #pragma unroll
            for (int r = 0; r < 4; r++) c[i][j][r] = 0.f;

    const int aRow = (lane & 15);
    const int aCol = ((lane >> 4) & 1) * 8;
    const int bRow = (lane & 7) + ((lane >> 4) << 3);
    const int bK   = ((lane >> 3) & 1) * 8;

    {
        #pragma unroll
        for (int t = 0; t < 4; t++) {
            const int ch = t * 128 + tid;
            const int r = ch >> 2, c8 = (ch & 3) << 3;
            cp16(aBase + 2u * (r * KPH + c8), Xp + (size_t)r * DM + c8);
            cp16(bBase + 2u * (r * KPH + c8), Wp + (size_t)r * DM + c8);
        }
        asm volatile("cp.async.commit_group;");
    }

    int buf = 0;
    for (int kt = 0; kt < DM / 32; kt++) {
        asm volatile("cp.async.wait_group 0;");
        __syncthreads();

        if (kt + 1 < DM / 32) {
            const int k0 = (kt + 1) * 32;
            const uint32_t ao = aBase + (buf ^ 1) * bufB;
            const uint32_t bo = bBase + (buf ^ 1) * bufB;
            #pragma unroll
            for (int t = 0; t < 4; t++) {
                const int ch = t * 128 + tid;
                const int r = ch >> 2, c8 = (ch & 3) << 3;
                cp16(ao + 2u * (r * KPH + c8), Xp + (size_t)r * DM + k0 + c8);
                cp16(bo + 2u * (r * KPH + c8), Wp + (size_t)r * DM + k0 + c8);
            }
            asm volatile("cp.async.commit_group;");
        }

        const uint32_t ab = aBase + buf * bufB;
        const uint32_t bb = bBase + buf * bufB;
        #pragma unroll
        for (int kc = 0; kc < 2; kc++) {
            uint32_t afr[4][4], bfr[4][4];
            #pragma unroll
            for (int mt = 0; mt < 4; mt++)
                ldsm_x4(afr[mt], ab + 2u * ((wm * 64 + mt * 16 + aRow) * KPH
                                            + aCol + kc * 16));
            #pragma unroll
            for (int nq = 0; nq < 4; nq++)
                ldsm_x4(bfr[nq], bb + 2u * ((wn * 64 + nq * 16 + bRow) * KPH
                                            + bK + kc * 16));
            #pragma unroll
            for (int mt = 0; mt < 4; mt++)
                #pragma unroll
                for (int nt = 0; nt < 8; nt++)
                    mma_f16(c[mt][nt], afr[mt],
                            bfr[nt >> 1][(nt & 1) * 2],
                            bfr[nt >> 1][(nt & 1) * 2 + 1]);
        }
        buf ^= 1;
    }

    #pragma unroll
    for (int mt = 0; mt < 4; mt++) {
        #pragma unroll
        for (int nt = 0; nt < 8; nt++) {
            const int row = m0 + wm * 64 + mt * 16 + (lane >> 2);
            const int col = e0 + wn * 64 + nt * 8 + 2 * (lane & 3);
            const float2 bv2 = *(const float2*)(bias + col);
            float2 v0, v1;
            v0.x = c[mt][nt][0] + bv2.x; v0.y = c[mt][nt][1] + bv2.y;
            v1.x = c[mt][nt][2] + bv2.x; v1.y = c[mt][nt][3] + bv2.y;
            *(float2*)(Y + (size_t)row * DM + col) = v0;
            *(float2*)(Y + (size_t)(row + 8) * DM + col) = v1;
        }
    }
}

// ---------------------------------------------------------------------------
// fp16 flash attention (R13 structure; softmax in log2 domain — Q carries
// the log2(e) factor, so probabilities use bare ex2.approx).
// ---------------------------------------------------------------------------
#define KP 72
#define FLASH_SMEM (2 * 128 * KP * 2)   // 36864 B
#define NT (SS / 128)                   // 16

__global__ void __launch_bounds__(128, 3) flash_f16(
    __half* __restrict__ outc)        // [B,S,DM] fp16
{
    extern __shared__ __half smh[];
    __half* Kh = smh;
    __half* Vh = smh + 128 * KP;

    const int tid  = threadIdx.x;
    const int lane = tid & 31;
    const int w    = tid >> 5;
    const int g    = lane >> 2;
    const int tig  = lane & 3;

    const int bh = blockIdx.y;
    const int b  = bh >> 4;
    const int h  = bh & 15;
    const int q0 = blockIdx.x * 64;

    const __half* Qg = g_qh + ((size_t)bh * SS + q0) * DK;
    const __half* Kg = g_kh + (size_t)bh * SS * DK;
    const __half* Vg = g_vh + (size_t)bh * SS * DK;

    const uint32_t kBase = (uint32_t)__cvta_generic_to_shared(Kh);
    const uint32_t vBase = (uint32_t)__cvta_generic_to_shared(Vh);

    const int sR0 = tid >> 3;
    const int sC8 = (tid & 7) << 3;

    uint32_t aq[4][4];
    {
        const __half* qr0 = Qg + (size_t)(w * 16 + g) * DK + 2 * tig;
        const __half* qr1 = qr0 + 8 * DK;
        #pragma unroll
        for (int kc = 0; kc < 4; kc++) {
            aq[kc][0] = *(const uint32_t*)(qr0 + kc * 16);
            aq[kc][1] = *(const uint32_t*)(qr1 + kc * 16);
            aq[kc][2] = *(const uint32_t*)(qr0 + kc * 16 + 8);
            aq[kc][3] = *(const uint32_t*)(qr1 + kc * 16 + 8);
        }
    }

    const uint32_t* MBr0 = g_mb + ((size_t)b * SS + q0 + w * 16 + g) * (SS / 32);
    const uint32_t* MBr1 = MBr0 + 8 * (SS / 32);

    float m0v = -1e30f, m1v = -1e30f, l0v = 0.f, l1v = 0.f;
    float of[8][4];
    #pragma unroll
    for (int j = 0; j < 8; j++)
        #pragma unroll
        for (int r = 0; r < 4; r++) of[j][r] = 0.f;

    const int bRow = (lane & 7) + ((lane >> 4) << 3);
    const int bK   = ((lane >> 3) & 1) * 8;
    const int vTile = lane >> 3;
    const int vR    = lane & 7;

    #pragma unroll
    for (int t = 0; t < 8; t++) {
        const int r = sR0 + t * 16;
        cp16(kBase + 2u * (r * KP + sC8), Kg + (size_t)r * DK + sC8);
    }
    asm volatile("cp.async.commit_group;");

    for (int kt = 0; kt < NT; kt++) {
        const __half* vp = Vg + (size_t)kt * 128 * DK;
        #pragma unroll
        for (int t = 0; t < 8; t++) {
            const int r = sR0 + t * 16;
            cp16(vBase + 2u * (r * KP + sC8), vp + (size_t)r * DK + sC8);
        }
        asm volatile("cp.async.commit_group;");

        asm volatile("cp.async.wait_group 1;");
        __syncthreads();

        float sfr[16][4];
        #pragma unroll
        for (int o = 0; o < 16; o++)
            #pragma unroll
            for (int r = 0; r < 4; r++) sfr[o][r] = 0.f;

        #pragma unroll
        for (int kc = 0; kc < 4; kc++) {
            #pragma unroll
            for (int nq = 0; nq < 8; nq++) {
                uint32_t bf[4];
                ldsm_x4(bf, kBase + 2u * ((nq * 16 + bRow) * KP + bK + kc * 16));
                mma_f16(sfr[2 * nq],     aq[kc], bf[0], bf[1]);
                mma_f16(sfr[2 * nq + 1], aq[kc], bf[2], bf[3]);
            }
        }

        __syncthreads();

        if (kt + 1 < NT) {
            const __half* kp = Kg + (size_t)(kt + 1) * 128 * DK;
            #pragma unroll
            for (int t = 0; t < 8; t++) {
                const int r = sR0 + t * 16;
                cp16(kBase + 2u * (r * KP + sC8), kp + (size_t)r * DK + sC8);
            }
            asm volatile("cp.async.commit_group;");
        }

        const uint4 mw0 = *(const uint4*)(MBr0 + kt * 4);
        const uint4 mw1 = *(const uint4*)(MBr1 + kt * 4);
        const uint32_t allw = mw0.x & mw0.y & mw0.z & mw0.w &
                              mw1.x & mw1.y & mw1.z & mw1.w;
        if (allw != 0xffffffffu) {
            #pragma unroll
            for (int o = 0; o < 16; o++) {
                const uint32_t wd0 = (o < 4) ? mw0.x : (o < 8) ? mw0.y
                                   : (o < 12) ? mw0.z : mw0.w;
                const uint32_t wd1 = (o < 4) ? mw1.x : (o < 8) ? mw1.y
                                   : (o < 12) ? mw1.z : mw1.w;
                const int bit = (o & 3) * 8 + 2 * tig;
                if (!((wd0 >> bit) & 1))       sfr[o][0] = -1e9f;
                if (!((wd0 >> (bit + 1)) & 1)) sfr[o][1] = -1e9f;
                if (!((wd1 >> bit) & 1))       sfr[o][2] = -1e9f;
                if (!((wd1 >> (bit + 1)) & 1)) sfr[o][3] = -1e9f;
            }
        }

        float pm0 = -1e30f, pm1 = -1e30f;
        #pragma unroll
        for (int o = 0; o < 16; o++) {
            pm0 = fmaxf(pm0, fmaxf(sfr[o][0], sfr[o][1]));
            pm1 = fmaxf(pm1, fmaxf(sfr[o][2], sfr[o][3]));
        }
        pm0 = fmaxf(pm0, __shfl_xor_sync(0xffffffffu, pm0, 1));
        pm0 = fmaxf(pm0, __shfl_xor_sync(0xffffffffu, pm0, 2));
        pm1 = fmaxf(pm1, __shfl_xor_sync(0xffffffffu, pm1, 1));
        pm1 = fmaxf(pm1, __shfl_xor_sync(0xffffffffu, pm1, 2));

        const float mn0 = fmaxf(m0v, pm0);
        const float mn1 = fmaxf(m1v, pm1);
        const float cr0 = ex2f(m0v - mn0);     // log2 domain
        const float cr1 = ex2f(m1v - mn1);
        m0v = mn0; m1v = mn1;

        float rs0 = 0.f, rs1 = 0.f;
        #pragma unroll
        for (int o = 0; o < 16; o++) {
            sfr[o][0] = ex2f(sfr[o][0] - mn0);
            sfr[o][1] = ex2f(sfr[o][1] - mn0);
            sfr[o][2] = ex2f(sfr[o][2] - mn1);
            sfr[o][3] = ex2f(sfr[o][3] - mn1);
            rs0 += sfr[o][0] + sfr[o][1];
            rs1 += sfr[o][2] + sfr[o][3];
        }
        rs0 += __shfl_xor_sync(0xffffffffu, rs0, 1);
        rs0 += __shfl_xor_sync(0xffffffffu, rs0, 2);
        rs1 += __shfl_xor_sync(0xffffffffu, rs1, 1);
        rs1 += __shfl_xor_sync(0xffffffffu, rs1, 2);
        l0v = l0v * cr0 + rs0;
        l1v = l1v * cr1 + rs1;

        #pragma unroll
        for (int j = 0; j < 8; j++) {
            of[j][0] *= cr0; of[j][1] *= cr0;
            of[j][2] *= cr1; of[j][3] *= cr1;
        }

        uint32_t ap[8][4];
        #pragma unroll
        for (int c = 0; c < 8; c++) {
            ap[c][0] = pack_h2(sfr[2 * c][0],     sfr[2 * c][1]);
            ap[c][1] = pack_h2(sfr[2 * c][2],     sfr[2 * c][3]);
            ap[c][2] = pack_h2(sfr[2 * c + 1][0], sfr[2 * c + 1][1]);
            ap[c][3] = pack_h2(sfr[2 * c + 1][2], sfr[2 * c + 1][3]);
        }

        if (kt + 1 < NT) {
            asm volatile("cp.async.wait_group 1;");
        } else {
            asm volatile("cp.async.wait_group 0;");
        }
        __syncthreads();

        #pragma unroll
        for (int c = 0; c < 8; c++) {
            #pragma unroll
            for (int nd = 0; nd < 4; nd++) {
                uint32_t bf[4];
                const int krow = c * 16 + (vTile & 1) * 8 + vR;
                const int dcol = nd * 16 + (vTile >> 1) * 8;
                ldsm_x4_t(bf, vBase + 2u * (krow * KP + dcol));
                mma_f16(of[2 * nd],     ap[c], bf[0], bf[1]);
                mma_f16(of[2 * nd + 1], ap[c], bf[2], bf[3]);
            }
        }

        __syncthreads();
    }

    const float inv0 = 1.0f / l0v;
    const float inv1 = 1.0f / l1v;
    const int row0 = q0 + w * 16 + g;
    #pragma unroll
    for (int j = 0; j < 8; j++) {
        const int col = h * DK + j * 8 + 2 * tig;
        __half2 h0 = __floats2half2_rn(of[j][0] * inv0, of[j][1] * inv0);
        __half2 h1 = __floats2half2_rn(of[j][2] * inv1, of[j][3] * inv1);
        *(__half2*)&outc[((size_t)(b * SS + row0)) * DM + col] = h0;
        *(__half2*)&outc[((size_t)(b * SS + row0 + 8)) * DM + col] = h1;
    }
}

// ---------------------------------------------------------------------------
extern "C" void kernel_launch(void* const* d_in, const int* in_sizes, int n_in,
                              void* d_out, int out_size)
{
    const float* q    = (const float*)d_in[0];
    const float* k    = (const float*)d_in[1];
    const float* v    = (const float*)d_in[2];
    const int*   mask = (const int*)  d_in[3];
    const float* bq   = (const float*)d_in[5];
    const float* bk   = (const float*)d_in[7];
    const float* bv   = (const float*)d_in[9];
    const float* Wq   = (const float*)d_in[4];
    const float* Wk   = (const float*)d_in[6];
    const float* Wv   = (const float*)d_in[8];
    const float* Wo   = (const float*)d_in[10];
    const float* bo   = (const float*)d_in[11];
    float* out = (float*)d_out;

    __half *ct, *w4;
    uint32_t* mb;
    cudaGetSymbolAddress((void**)&ct, g_ct);
    cudaGetSymbolAddress((void**)&w4, g_w4);
    cudaGetSymbolAddress((void**)&mb, g_mb);

    const dim3 bb(128);
    const int CONV_BLOCKS = (int)((3 * NX + 4 * NW) / (256 * 8));   // 14336

    pack_mask<<<(BB * SS * SS) / 256, 256>>>(mask, mb);
    convert_all<<<CONV_BLOCKS, 256>>>(q, k, v, Wq, Wk, Wv, Wo);

    // batched Q/K/V projection — one launch, grid.z = 3
    gemm_qkv<<<dim3(MROWS / 128, DM / 128, 3), bb>>>(bq, bk, bv);

    cudaFuncSetAttribute(flash_f16, cudaFuncAttributeMaxDynamicSharedMemorySize,
                         FLASH_SMEM);
    flash_f16<<<dim3(SS / 64, BB * HH), 128, FLASH_SMEM>>>(ct);

    gemm_out<<<dim3(MROWS / 128, DM / 128), bb>>>(ct, w4 + 3 * NW, bo, out);
}

// round 16
// speedup vs baseline: 1.4181x; 1.4181x over previous
#include <cuda_runtime.h>
#include <cuda_fp16.h>
#include <cstdint>

#define BB 4
#define SS 2048
#define DM 1024
#define HH 16
#define DK 64
#define MROWS (BB * SS)   // 8192
#define NX ((size_t)MROWS * DM)   // 8388608
#define NW ((size_t)DM * DM)      // 1048576

// scratch (allocation-free rule: __device__ globals)
__device__ __half   g_qh[BB * HH * SS * DK];   // pre-scaled by 0.125*log2(e)
__device__ __half   g_kh[BB * HH * SS * DK];
__device__ __half   g_vh[BB * HH * SS * DK];
__device__ __half   g_ct[BB * SS * DM];        // fp16 concat
__device__ __half   g_x3[3 * NX];              // fp16 q|k|v
__device__ __half   g_w4[4 * NW];              // fp16 Wq|Wk|Wv|Wo
__device__ uint32_t g_mb[BB * SS * (SS / 32)]; // bit-packed mask (2MB)

#define QSCALE (0.125f * 1.44269504088896f)    // 1/sqrt(dk) * log2(e)

// ---------------------------------------------------------------------------
// helpers
// ---------------------------------------------------------------------------
__device__ __forceinline__ void ldsm_x4(uint32_t* r, uint32_t addr) {
    asm volatile("ldmatrix.sync.aligned.m8n8.x4.shared.b16 {%0,%1,%2,%3}, [%4];"
                 : "=r"(r[0]), "=r"(r[1]), "=r"(r[2]), "=r"(r[3]) : "r"(addr));
}

__device__ __forceinline__ void ldsm_x4_t(uint32_t* r, uint32_t addr) {
    asm volatile("ldmatrix.sync.aligned.m8n8.x4.trans.shared.b16 {%0,%1,%2,%3}, [%4];"
                 : "=r"(r[0]), "=r"(r[1]), "=r"(r[2]), "=r"(r[3]) : "r"(addr));
}

__device__ __forceinline__ void mma_f16(float* c, const uint32_t* a,
                                        uint32_t b0, uint32_t b1) {
    asm volatile(
        "mma.sync.aligned.m16n8k16.row.col.f32.f16.f16.f32 "
        "{%0,%1,%2,%3},{%4,%5,%6,%7},{%8,%9},{%0,%1,%2,%3};"
        : "+f"(c[0]), "+f"(c[1]), "+f"(c[2]), "+f"(c[3])
        : "r"(a[0]), "r"(a[1]), "r"(a[2]), "r"(a[3]), "r"(b0), "r"(b1));
}

__device__ __forceinline__ uint32_t pack_h2(float lo, float hi) {
    __half2 h = __floats2half2_rn(lo, hi);
    return *(uint32_t*)&h;
}

__device__ __forceinline__ void cp16(uint32_t dst, const void* src) {
    asm volatile("cp.async.ca.shared.global [%0], [%1], 16;"
                 :: "r"(dst), "l"(src));
}

__device__ __forceinline__ float ex2f(float x) {
    float r;
    asm("ex2.approx.ftz.f32 %0, %1;" : "=f"(r) : "f"(x));
    return r;
}

// ---------------------------------------------------------------------------
// one-shot fp32 -> fp16 for q,k,v,Wq,Wk,Wv,Wo (8 elems/thread)
// ---------------------------------------------------------------------------
__global__ void convert_all(const float* __restrict__ q, const float* __restrict__ k,
                            const float* __restrict__ v, const float* __restrict__ Wq,
                            const float* __restrict__ Wk, const float* __restrict__ Wv,
                            const float* __restrict__ Wo) {
    const size_t i = ((size_t)blockIdx.x * blockDim.x + threadIdx.x) * 8;
    const float* src;
    __half* dst;
    if (i < NX)            { src = q  + i;           dst = g_x3 + i; }
    else if (i < 2 * NX)   { src = k  + (i - NX);    dst = g_x3 + i; }
    else if (i < 3 * NX)   { src = v  + (i - 2*NX);  dst = g_x3 + i; }
    else {
        const size_t j = i - 3 * NX;
        if (j < NW)          { src = Wq + j;          dst = g_w4 + j; }
        else if (j < 2 * NW) { src = Wk + (j - NW);   dst = g_w4 + j; }
        else if (j < 3 * NW) { src = Wv + (j - 2*NW); dst = g_w4 + j; }
        else                 { src = Wo + (j - 3*NW); dst = g_w4 + j; }
    }
    const float4 a = *(const float4*)(src);
    const float4 b = *(const float4*)(src + 4);
    __half2 h[4];
    h[0] = __floats2half2_rn(a.x, a.y);
    h[1] = __floats2half2_rn(a.z, a.w);
    h[2] = __floats2half2_rn(b.x, b.y);
    h[3] = __floats2half2_rn(b.z, b.w);
    *(uint4*)dst = *(const uint4*)h;
}

// ---------------------------------------------------------------------------
// mask bit-pack
// ---------------------------------------------------------------------------
__global__ void pack_mask(const int* __restrict__ mask, uint32_t* __restrict__ mb) {
    const size_t g = (size_t)blockIdx.x * blockDim.x + threadIdx.x;
    const uint32_t word = __ballot_sync(0xffffffffu, mask[g] != 0);
    if ((threadIdx.x & 31) == 0) mb[g >> 5] = word;
}

// ---------------------------------------------------------------------------
// fp16 GEMM (R13-validated, byte-identical): 128x128x32 CTA tile, 128 threads
// (4 warps 2x2), 64x64 warp tile, m16n8k16, cp.async double buffer.
// ---------------------------------------------------------------------------
#define KPH 40

template <bool HEAD_OUT>
__global__ void __launch_bounds__(128, 2) gemm_f16(
    const __half* __restrict__ X,     // [MROWS, DM] fp16
    const __half* __restrict__ W,     // [DM(e), DM(d)] fp16
    const float* __restrict__ bias,   // [DM]
    void* __restrict__ Yv,
    float scale)
{
    __shared__ __half Ah[2][128 * KPH];
    __shared__ __half Bh[2][128 * KPH];

    const int tid  = threadIdx.x;
    const int lane = tid & 31;
    const int warp = tid >> 5;
    const int wm   = warp >> 1;          // 0..1 (64 rows)
    const int wn   = warp & 1;           // 0..1 (64 cols)
    const int m0   = blockIdx.x * 128;
    const int e0   = blockIdx.y * 128;

    const uint32_t aBase = (uint32_t)__cvta_generic_to_shared(&Ah[0][0]);
    const uint32_t bBase = (uint32_t)__cvta_generic_to_shared(&Bh[0][0]);
    const uint32_t bufB  = 128 * KPH * 2;

    const __half* Xp = X + (size_t)m0 * DM;
    const __half* Wp = W + (size_t)e0 * DM;

    float c[4][8][4];
    #pragma unroll
    for (int i = 0; i < 4; i++)
        #pragma unroll
        for (int j = 0; j < 8; j++)
            #pragma unroll
            for (int r = 0; r < 4; r++) c[i][j][r] = 0.f;

    const int aRow = (lane & 15);
    const int aCol = ((lane >> 4) & 1) * 8;
    const int bRow = (lane & 7) + ((lane >> 4) << 3);
    const int bK   = ((lane >> 3) & 1) * 8;

    {
        #pragma unroll
        for (int t = 0; t < 4; t++) {
            const int ch = t * 128 + tid;
            const int r = ch >> 2, c8 = (ch & 3) << 3;
            cp16(aBase + 2u * (r * KPH + c8), Xp + (size_t)r * DM + c8);
            cp16(bBase + 2u * (r * KPH + c8), Wp + (size_t)r * DM + c8);
        }
        asm volatile("cp.async.commit_group;");
    }

    int buf = 0;
    for (int kt = 0; kt < DM / 32; kt++) {
        asm volatile("cp.async.wait_group 0;");
        __syncthreads();

        if (kt + 1 < DM / 32) {
            const int k0 = (kt + 1) * 32;
            const uint32_t ao = aBase + (buf ^ 1) * bufB;
            const uint32_t bo = bBase + (buf ^ 1) * bufB;
            #pragma unroll
            for (int t = 0; t < 4; t++) {
                const int ch = t * 128 + tid;
                const int r = ch >> 2, c8 = (ch & 3) << 3;
                cp16(ao + 2u * (r * KPH + c8), Xp + (size_t)r * DM + k0 + c8);
                cp16(bo + 2u * (r * KPH + c8), Wp + (size_t)r * DM + k0 + c8);
            }
            asm volatile("cp.async.commit_group;");
        }

        const uint32_t ab = aBase + buf * bufB;
        const uint32_t bb = bBase + buf * bufB;
        #pragma unroll
        for (int kc = 0; kc < 2; kc++) {
            uint32_t afr[4][4], bfr[4][4];
            #pragma unroll
            for (int mt = 0; mt < 4; mt++)
                ldsm_x4(afr[mt], ab + 2u * ((wm * 64 + mt * 16 + aRow) * KPH
                                            + aCol + kc * 16));
            #pragma unroll
            for (int nq = 0; nq < 4; nq++)
                ldsm_x4(bfr[nq], bb + 2u * ((wn * 64 + nq * 16 + bRow) * KPH
                                            + bK + kc * 16));
            #pragma unroll
            for (int mt = 0; mt < 4; mt++)
                #pragma unroll
                for (int nt = 0; nt < 8; nt++)
                    mma_f16(c[mt][nt], afr[mt],
                            bfr[nt >> 1][(nt & 1) * 2],
                            bfr[nt >> 1][(nt & 1) * 2 + 1]);
        }
        buf ^= 1;
    }

    // epilogue
    #pragma unroll
    for (int mt = 0; mt < 4; mt++) {
        #pragma unroll
        for (int nt = 0; nt < 8; nt++) {
            const int row = m0 + wm * 64 + mt * 16 + (lane >> 2);
            const int col = e0 + wn * 64 + nt * 8 + 2 * (lane & 3);
            const float2 bv = *(const float2*)(bias + col);
            float2 v0, v1;
            v0.x = (c[mt][nt][0] + bv.x) * scale;
            v0.y = (c[mt][nt][1] + bv.y) * scale;
            v1.x = (c[mt][nt][2] + bv.x) * scale;
            v1.y = (c[mt][nt][3] + bv.y) * scale;
            if (HEAD_OUT) {
                __half* Y = (__half*)Yv;
                const int h = col >> 6, d = col & 63;
                const int b0_ = row >> 11, s0 = row & (SS - 1);
                __half2 h0 = __floats2half2_rn(v0.x, v0.y);
                __half2 h1 = __floats2half2_rn(v1.x, v1.y);
                *(__half2*)(Y + ((size_t)((b0_ * HH + h) * SS + s0)) * DK + d) = h0;
                *(__half2*)(Y + ((size_t)((b0_ * HH + h) * SS + s0 + 8)) * DK + d) = h1;
            } else {
                float* Y = (float*)Yv;
                *(float2*)(Y + (size_t)row * DM + col) = v0;
                *(float2*)(Y + (size_t)(row + 8) * DM + col) = v1;
            }
        }
    }
}

// ---------------------------------------------------------------------------
// fp16 flash attention (R13 structure; softmax in log2 domain — Q carries
// the log2(e) factor, so probabilities use bare ex2.approx).
// ---------------------------------------------------------------------------
#define KP 72
#define FLASH_SMEM (2 * 128 * KP * 2)   // 36864 B
#define NT (SS / 128)                   // 16

__global__ void __launch_bounds__(128, 3) flash_f16(
    __half* __restrict__ outc)        // [B,S,DM] fp16
{
    extern __shared__ __half smh[];
    __half* Kh = smh;
    __half* Vh = smh + 128 * KP;

    const int tid  = threadIdx.x;
    const int lane = tid & 31;
    const int w    = tid >> 5;
    const int g    = lane >> 2;
    const int tig  = lane & 3;

    const int bh = blockIdx.y;
    const int b  = bh >> 4;
    const int h  = bh & 15;
    const int q0 = blockIdx.x * 64;

    const __half* Qg = g_qh + ((size_t)bh * SS + q0) * DK;
    const __half* Kg = g_kh + (size_t)bh * SS * DK;
    const __half* Vg = g_vh + (size_t)bh * SS * DK;

    const uint32_t kBase = (uint32_t)__cvta_generic_to_shared(Kh);
    const uint32_t vBase = (uint32_t)__cvta_generic_to_shared(Vh);

    const int sR0 = tid >> 3;
    const int sC8 = (tid & 7) << 3;

    uint32_t aq[4][4];
    {
        const __half* qr0 = Qg + (size_t)(w * 16 + g) * DK + 2 * tig;
        const __half* qr1 = qr0 + 8 * DK;
        #pragma unroll
        for (int kc = 0; kc < 4; kc++) {
            aq[kc][0] = *(const uint32_t*)(qr0 + kc * 16);
            aq[kc][1] = *(const uint32_t*)(qr1 + kc * 16);
            aq[kc][2] = *(const uint32_t*)(qr0 + kc * 16 + 8);
            aq[kc][3] = *(const uint32_t*)(qr1 + kc * 16 + 8);
        }
    }

    const uint32_t* MBr0 = g_mb + ((size_t)b * SS + q0 + w * 16 + g) * (SS / 32);
    const uint32_t* MBr1 = MBr0 + 8 * (SS / 32);

    float m0v = -1e30f, m1v = -1e30f, l0v = 0.f, l1v = 0.f;
    float of[8][4];
    #pragma unroll
    for (int j = 0; j < 8; j++)
        #pragma unroll
        for (int r = 0; r < 4; r++) of[j][r] = 0.f;

    const int bRow = (lane & 7) + ((lane >> 4) << 3);
    const int bK   = ((lane >> 3) & 1) * 8;
    const int vTile = lane >> 3;
    const int vR    = lane & 7;

    #pragma unroll
    for (int t = 0; t < 8; t++) {
        const int r = sR0 + t * 16;
        cp16(kBase + 2u * (r * KP + sC8), Kg + (size_t)r * DK + sC8);
    }
    asm volatile("cp.async.commit_group;");

    for (int kt = 0; kt < NT; kt++) {
        const __half* vp = Vg + (size_t)kt * 128 * DK;
        #pragma unroll
        for (int t = 0; t < 8; t++) {
            const int r = sR0 + t * 16;
            cp16(vBase + 2u * (r * KP + sC8), vp + (size_t)r * DK + sC8);
        }
        asm volatile("cp.async.commit_group;");

        asm volatile("cp.async.wait_group 1;");
        __syncthreads();

        float sfr[16][4];
        #pragma unroll
        for (int o = 0; o < 16; o++)
            #pragma unroll
            for (int r = 0; r < 4; r++) sfr[o][r] = 0.f;

        #pragma unroll
        for (int kc = 0; kc < 4; kc++) {
            #pragma unroll
            for (int nq = 0; nq < 8; nq++) {
                uint32_t bf[4];
                ldsm_x4(bf, kBase + 2u * ((nq * 16 + bRow) * KP + bK + kc * 16));
                mma_f16(sfr[2 * nq],     aq[kc], bf[0], bf[1]);
                mma_f16(sfr[2 * nq + 1], aq[kc], bf[2], bf[3]);
            }
        }

        __syncthreads();

        if (kt + 1 < NT) {
            const __half* kp = Kg + (size_t)(kt + 1) * 128 * DK;
            #pragma unroll
            for (int t = 0; t < 8; t++) {
                const int r = sR0 + t * 16;
                cp16(kBase + 2u * (r * KP + sC8), kp + (size_t)r * DK + sC8);
            }
            asm volatile("cp.async.commit_group;");
        }

        const uint4 mw0 = *(const uint4*)(MBr0 + kt * 4);
        const uint4 mw1 = *(const uint4*)(MBr1 + kt * 4);
        const uint32_t allw = mw0.x & mw0.y & mw0.z & mw0.w &
                              mw1.x & mw1.y & mw1.z & mw1.w;
        if (allw != 0xffffffffu) {
            #pragma unroll
            for (int o = 0; o < 16; o++) {
                const uint32_t wd0 = (o < 4) ? mw0.x : (o < 8) ? mw0.y
                                   : (o < 12) ? mw0.z : mw0.w;
                const uint32_t wd1 = (o < 4) ? mw1.x : (o < 8) ? mw1.y
                                   : (o < 12) ? mw1.z : mw1.w;
                const int bit = (o & 3) * 8 + 2 * tig;
                if (!((wd0 >> bit) & 1))       sfr[o][0] = -1e9f;
                if (!((wd0 >> (bit + 1)) & 1)) sfr[o][1] = -1e9f;
                if (!((wd1 >> bit) & 1))       sfr[o][2] = -1e9f;
                if (!((wd1 >> (bit + 1)) & 1)) sfr[o][3] = -1e9f;
            }
        }

        float pm0 = -1e30f, pm1 = -1e30f;
        #pragma unroll
        for (int o = 0; o < 16; o++) {
            pm0 = fmaxf(pm0, fmaxf(sfr[o][0], sfr[o][1]));
            pm1 = fmaxf(pm1, fmaxf(sfr[o][2], sfr[o][3]));
        }
        pm0 = fmaxf(pm0, __shfl_xor_sync(0xffffffffu, pm0, 1));
        pm0 = fmaxf(pm0, __shfl_xor_sync(0xffffffffu, pm0, 2));
        pm1 = fmaxf(pm1, __shfl_xor_sync(0xffffffffu, pm1, 1));
        pm1 = fmaxf(pm1, __shfl_xor_sync(0xffffffffu, pm1, 2));

        const float mn0 = fmaxf(m0v, pm0);
        const float mn1 = fmaxf(m1v, pm1);
        const float cr0 = ex2f(m0v - mn0);     // log2 domain
        const float cr1 = ex2f(m1v - mn1);
        m0v = mn0; m1v = mn1;

        float rs0 = 0.f, rs1 = 0.f;
        #pragma unroll
        for (int o = 0; o < 16; o++) {
            sfr[o][0] = ex2f(sfr[o][0] - mn0);
            sfr[o][1] = ex2f(sfr[o][1] - mn0);
            sfr[o][2] = ex2f(sfr[o][2] - mn1);
            sfr[o][3] = ex2f(sfr[o][3] - mn1);
            rs0 += sfr[o][0] + sfr[o][1];
            rs1 += sfr[o][2] + sfr[o][3];
        }
        rs0 += __shfl_xor_sync(0xffffffffu, rs0, 1);
        rs0 += __shfl_xor_sync(0xffffffffu, rs0, 2);
        rs1 += __shfl_xor_sync(0xffffffffu, rs1, 1);
        rs1 += __shfl_xor_sync(0xffffffffu, rs1, 2);
        l0v = l0v * cr0 + rs0;
        l1v = l1v * cr1 + rs1;

        #pragma unroll
        for (int j = 0; j < 8; j++) {
            of[j][0] *= cr0; of[j][1] *= cr0;
            of[j][2] *= cr1; of[j][3] *= cr1;
        }

        uint32_t ap[8][4];
        #pragma unroll
        for (int c = 0; c < 8; c++) {
            ap[c][0] = pack_h2(sfr[2 * c][0],     sfr[2 * c][1]);
            ap[c][1] = pack_h2(sfr[2 * c][2],     sfr[2 * c][3]);
            ap[c][2] = pack_h2(sfr[2 * c + 1][0], sfr[2 * c + 1][1]);
            ap[c][3] = pack_h2(sfr[2 * c + 1][2], sfr[2 * c + 1][3]);
        }

        if (kt + 1 < NT) {
            asm volatile("cp.async.wait_group 1;");
        } else {
            asm volatile("cp.async.wait_group 0;");
        }
        __syncthreads();

        #pragma unroll
        for (int c = 0; c < 8; c++) {
            #pragma unroll
            for (int nd = 0; nd < 4; nd++) {
                uint32_t bf[4];
                const int krow = c * 16 + (vTile & 1) * 8 + vR;
                const int dcol = nd * 16 + (vTile >> 1) * 8;
                ldsm_x4_t(bf, vBase + 2u * (krow * KP + dcol));
                mma_f16(of[2 * nd],     ap[c], bf[0], bf[1]);
                mma_f16(of[2 * nd + 1], ap[c], bf[2], bf[3]);
            }
        }

        __syncthreads();
    }

    const float inv0 = 1.0f / l0v;
    const float inv1 = 1.0f / l1v;
    const int row0 = q0 + w * 16 + g;
    #pragma unroll
    for (int j = 0; j < 8; j++) {
        const int col = h * DK + j * 8 + 2 * tig;
        __half2 h0 = __floats2half2_rn(of[j][0] * inv0, of[j][1] * inv0);
        __half2 h1 = __floats2half2_rn(of[j][2] * inv1, of[j][3] * inv1);
        *(__half2*)&outc[((size_t)(b * SS + row0)) * DM + col] = h0;
        *(__half2*)&outc[((size_t)(b * SS + row0 + 8)) * DM + col] = h1;
    }
}

// ---------------------------------------------------------------------------
extern "C" void kernel_launch(void* const* d_in, const int* in_sizes, int n_in,
                              void* d_out, int out_size)
{
    const float* q    = (const float*)d_in[0];
    const float* k    = (const float*)d_in[1];
    const float* v    = (const float*)d_in[2];
    const int*   mask = (const int*)  d_in[3];
    const float* Wq   = (const float*)d_in[4];
    const float* bq   = (const float*)d_in[5];
    const float* Wk   = (const float*)d_in[6];
    const float* bk   = (const float*)d_in[7];
    const float* Wv   = (const float*)d_in[8];
    const float* bv   = (const float*)d_in[9];
    const float* Wo   = (const float*)d_in[10];
    const float* bo   = (const float*)d_in[11];
    float* out = (float*)d_out;

    __half *qh, *kh, *vh, *ct, *x3, *w4;
    uint32_t* mb;
    cudaGetSymbolAddress((void**)&qh, g_qh);
    cudaGetSymbolAddress((void**)&kh, g_kh);
    cudaGetSymbolAddress((void**)&vh, g_vh);
    cudaGetSymbolAddress((void**)&ct, g_ct);
    cudaGetSymbolAddress((void**)&x3, g_x3);
    cudaGetSymbolAddress((void**)&w4, g_w4);
    cudaGetSymbolAddress((void**)&mb, g_mb);

    const dim3 gg(MROWS / 128, DM / 128);
    const dim3 bb(128);
    const int CONV_BLOCKS = (int)((3 * NX + 4 * NW) / (256 * 8));   // 14336

    pack_mask<<<(BB * SS * SS) / 256, 256>>>(mask, mb);
    convert_all<<<CONV_BLOCKS, 256>>>(q, k, v, Wq, Wk, Wv, Wo);

    gemm_f16<true><<<gg, bb>>>(x3,           w4,          bq, qh, QSCALE);
    gemm_f16<true><<<gg, bb>>>(x3 + NX,      w4 + NW,     bk, kh, 1.0f);
    gemm_f16<true><<<gg, bb>>>(x3 + 2 * NX,  w4 + 2 * NW, bv, vh, 1.0f);

    cudaFuncSetAttribute(flash_f16, cudaFuncAttributeMaxDynamicSharedMemorySize,
                         FLASH_SMEM);
    flash_f16<<<dim3(SS / 64, BB * HH), 128, FLASH_SMEM>>>(ct);

    gemm_f16<false><<<gg, bb>>>(ct, w4 + 3 * NW, bo, out, 1.0f);
}